// round 5
// baseline (speedup 1.0000x reference)
#include <cuda_runtime.h>
#include <cuda_bf16.h>
#include <math.h>
#include <stdint.h>

// ---------------------------------------------------------------------------
#define D_MODEL   256
#define DEPTH     2
#define D_INNER   512
#define D_STATE   16
#define D_CONV    4
#define DT_RANK   16
#define BATCH     2
#define SEQLEN    2048
#define NTOK      (BATCH * SEQLEN)          // 4096
#define DBL_COLS  (DT_RANK + 2 * D_STATE)   // 48

#define NCHUNK    32
#define CLEN      (SEQLEN / NCHUNK)         // 64
#define XP_SK     4                          // x_proj split-K slices

// ---------------------------------------------------------------------------
// Scratch
// ---------------------------------------------------------------------------
__device__ float  g_xz   [NTOK * 2 * D_INNER];
__device__ float  g_dbl  [NTOK * DBL_COLS];
__device__ float  g_part [XP_SK * NTOK * DBL_COLS];
__device__ float  g_y    [NTOK * D_INNER];
__device__ float  g_cA   [BATCH * NCHUNK * D_INNER * D_STATE];
__device__ float  g_cH   [BATCH * NCHUNK * D_INNER * D_STATE];
__device__ float  g_hs   [BATCH * NCHUNK * D_INNER * D_STATE];
__device__ float2 g_stats[NTOK];             // (mu, inv_std) per token

// ---------------------------------------------------------------------------
// cp.async helpers
// ---------------------------------------------------------------------------
__device__ __forceinline__ uint32_t smem_u32(const void* p) {
    uint32_t a;
    asm("{.reg .u64 t; cvta.to.shared.u64 t, %1; cvt.u32.u64 %0, t;}"
        : "=r"(a) : "l"(p));
    return a;
}
__device__ __forceinline__ void cp_async16(void* dst, const void* src) {
    asm volatile("cp.async.ca.shared.global [%0], [%1], 16;"
                 :: "r"(smem_u32(dst)), "l"(src));
}
__device__ __forceinline__ void cp_async16_z(void* dst, const void* src, bool ok) {
    int sz = ok ? 16 : 0;
    asm volatile("cp.async.ca.shared.global [%0], [%1], 16, %2;"
                 :: "r"(smem_u32(dst)), "l"(src), "r"(sz));
}
#define CP_COMMIT() asm volatile("cp.async.commit_group;")
#define CP_WAIT0()  asm volatile("cp.async.wait_group 0;")

__device__ __forceinline__ float silu_f(float v) {
    return v / (1.f + __expf(-v));
}

// ---------------------------------------------------------------------------
// LN stats: one warp per token (256-wide rows), grid = NTOK/8 blocks of 256
// ---------------------------------------------------------------------------
__global__ void ln_stats_kernel(const float* __restrict__ x,
                                float2* __restrict__ stats)
{
    int t    = blockIdx.x * 8 + (threadIdx.x >> 5);
    int lane = threadIdx.x & 31;
    const float4* p = (const float4*)(x + (size_t)t * D_MODEL);
    float s = 0.f, q = 0.f;
    #pragma unroll
    for (int h = 0; h < 2; h++) {
        float4 v = p[lane + 32 * h];
        s += v.x + v.y + v.z + v.w;
        q += v.x * v.x + v.y * v.y + v.z * v.z + v.w * v.w;
    }
    #pragma unroll
    for (int o = 16; o > 0; o >>= 1) {
        s += __shfl_xor_sync(0xffffffffu, s, o);
        q += __shfl_xor_sync(0xffffffffu, q, o);
    }
    if (lane == 0) {
        float mu  = s * (1.f / D_MODEL);
        float var = q * (1.f / D_MODEL) - mu * mu;
        stats[t] = make_float2(mu, rsqrtf(var + 1e-5f));
    }
}

// ---------------------------------------------------------------------------
// tf32 GEMM, double-buffered. C[M,N] = A'[M,K] @ W[N,K]^T
//   LN=true : A' = (A - mu)*inv*lnw[k] + lnb[k]   (A via registers)
//   LN=false: A' = A                              (A via cp.async)
//   MODE 0: store | MODE 2: C += acc
// BM = 64*MTILES (MTILES 1 or 2), BN=64, BK=16, 256 thr, 8 warps (4x2).
// ---------------------------------------------------------------------------
template <int MODE, int MTILES, bool LN>
__global__ __launch_bounds__(256)
void gemm_fused(const float* __restrict__ A, int lda,
                const float* __restrict__ W, int ldw,
                float*       __restrict__ C, int ldc,
                int N, int K,
                const float2* __restrict__ stats,
                const float*  __restrict__ lnw,
                const float*  __restrict__ lnb)
{
    const int BM = 64 * MTILES, BN = 64, BK = 16, LDS = 20;
    __shared__ uint32_t As[2][BM * LDS];
    __shared__ uint32_t Bs[2][BN * LDS];

    int tid  = threadIdx.x;
    int lane = tid & 31;
    int warp = tid >> 5;
    int m0 = blockIdx.y * BM;
    int n0 = blockIdx.x * BN;
    int wm = (warp >> 1) * 16 * MTILES;
    int wn = (warp & 1) * 32;
    int gr = lane >> 2;
    int gc = lane & 3;

    float acc[MTILES][4][4];
    #pragma unroll
    for (int mi = 0; mi < MTILES; mi++)
        #pragma unroll
        for (int ni = 0; ni < 4; ni++)
            #pragma unroll
            for (int e = 0; e < 4; e++) acc[mi][ni][e] = 0.f;

    int lrow = tid >> 2;           // 0..63
    int lcol = (tid & 3) * 4;      // 0,4,8,12

    float2 st[MTILES];
    if (LN) {
        #pragma unroll
        for (int h = 0; h < MTILES; h++)
            st[h] = __ldg(&stats[m0 + lrow + h * 64]);
    }

    auto issueW = [&](int k0, int buf) {
        int r = lrow;
        bool ok = (n0 + r) < N;
        const float* src = ok ? &W[(size_t)(n0 + r) * ldw + k0 + lcol] : W;
        cp_async16_z(&Bs[buf][r * LDS + lcol], src, ok);
    };
    auto issueA = [&](int k0, int buf) {   // cp.async path (LN=false)
        #pragma unroll
        for (int h = 0; h < MTILES; h++) {
            int r = lrow + h * 64;
            cp_async16(&As[buf][r * LDS + lcol],
                       &A[(size_t)(m0 + r) * lda + k0 + lcol]);
        }
    };

    float4 areg[MTILES], wreg, breg;
    auto loadA = [&](int k0) {             // register path (LN=true)
        #pragma unroll
        for (int h = 0; h < MTILES; h++)
            areg[h] = *(const float4*)&A[(size_t)(m0 + lrow + h * 64) * lda + k0 + lcol];
        wreg = *(const float4*)&lnw[k0 + lcol];
        breg = *(const float4*)&lnb[k0 + lcol];
    };
    auto storeA = [&](int buf) {
        #pragma unroll
        for (int h = 0; h < MTILES; h++) {
            float4 v = areg[h];
            float mu = st[h].x, inv = st[h].y;
            uint32_t* dst = &As[buf][(lrow + h * 64) * LDS + lcol];
            dst[0] = __float_as_uint((v.x - mu) * inv * wreg.x + breg.x);
            dst[1] = __float_as_uint((v.y - mu) * inv * wreg.y + breg.y);
            dst[2] = __float_as_uint((v.z - mu) * inv * wreg.z + breg.z);
            dst[3] = __float_as_uint((v.w - mu) * inv * wreg.w + breg.w);
        }
    };

    int nk = K / BK;
    if (LN) { issueW(0, 0); CP_COMMIT(); loadA(0); }
    else    { issueA(0, 0); issueW(0, 0); CP_COMMIT(); }

    for (int i = 0; i < nk; i++) {
        int buf = i & 1;
        if (LN) storeA(buf);
        CP_WAIT0();
        __syncthreads();
        if (i + 1 < nk) {
            if (LN) { issueW((i + 1) * BK, buf ^ 1); CP_COMMIT(); loadA((i + 1) * BK); }
            else    { issueA((i + 1) * BK, buf ^ 1); issueW((i + 1) * BK, buf ^ 1); CP_COMMIT(); }
        }

        #pragma unroll
        for (int ks = 0; ks < BK; ks += 8) {
            uint32_t a[MTILES][4], b[4][2];
            #pragma unroll
            for (int mi = 0; mi < MTILES; mi++) {
                int rb = wm + mi * 16 + gr;
                a[mi][0] = As[buf][rb * LDS + ks + gc];
                a[mi][1] = As[buf][(rb + 8) * LDS + ks + gc];
                a[mi][2] = As[buf][rb * LDS + ks + gc + 4];
                a[mi][3] = As[buf][(rb + 8) * LDS + ks + gc + 4];
            }
            #pragma unroll
            for (int ni = 0; ni < 4; ni++) {
                int rb = wn + ni * 8 + gr;
                b[ni][0] = Bs[buf][rb * LDS + ks + gc];
                b[ni][1] = Bs[buf][rb * LDS + ks + gc + 4];
            }
            #pragma unroll
            for (int mi = 0; mi < MTILES; mi++)
                #pragma unroll
                for (int ni = 0; ni < 4; ni++)
                    asm volatile(
                        "mma.sync.aligned.m16n8k8.row.col.f32.tf32.tf32.f32 "
                        "{%0,%1,%2,%3}, {%4,%5,%6,%7}, {%8,%9}, {%0,%1,%2,%3};"
                        : "+f"(acc[mi][ni][0]), "+f"(acc[mi][ni][1]),
                          "+f"(acc[mi][ni][2]), "+f"(acc[mi][ni][3])
                        : "r"(a[mi][0]), "r"(a[mi][1]), "r"(a[mi][2]), "r"(a[mi][3]),
                          "r"(b[ni][0]), "r"(b[ni][1]));
        }
        if (LN && i + 1 < nk) ; // next storeA happens at top of next iter
        if (!LN) ;
        __syncthreads();
    }

    #pragma unroll
    for (int mi = 0; mi < MTILES; mi++) {
        #pragma unroll
        for (int ni = 0; ni < 4; ni++) {
            #pragma unroll
            for (int e = 0; e < 4; e++) {
                int row = m0 + wm + mi * 16 + gr + ((e >= 2) ? 8 : 0);
                int col = n0 + wn + ni * 8 + gc * 2 + (e & 1);
                if (col < N) {
                    float v = acc[mi][ni][e];
                    if (MODE == 2) v += C[(size_t)row * ldc + col];
                    C[(size_t)row * ldc + col] = v;
                }
            }
        }
    }
}

// ---------------------------------------------------------------------------
// x_proj GEMM with fused depthwise conv + SiLU on the A operand.
// part[z][M,48] = conv_silu(xz_xi)[:, z*128:(z+1)*128] @ xpw[:, z*128:..]^T
// Grid: (1, M/128, XP_SK). Single-buffered smem staging, 8 k-iters.
// ---------------------------------------------------------------------------
__global__ __launch_bounds__(256)
void xproj_conv_gemm(const float* __restrict__ xz,
                     const float* __restrict__ cw,
                     const float* __restrict__ cb,
                     const float* __restrict__ xpw,
                     float*       __restrict__ part)
{
    const int BM = 128, BK = 16, LDS = 20, KS = D_INNER / XP_SK;  // 128
    __shared__ uint32_t As[BM * LDS];
    __shared__ uint32_t Bs[64 * LDS];
    __shared__ float    s_xz[(BM + 3) * 16];

    int tid  = threadIdx.x;
    int lane = tid & 31;
    int warp = tid >> 5;
    int m0 = blockIdx.y * BM;
    int z  = blockIdx.z;
    int wm = (warp >> 1) * 32;
    int wn = (warp & 1) * 32;
    int gr = lane >> 2;
    int gc = lane & 3;
    bool lead_tile = ((m0 & (SEQLEN - 1)) == 0);

    float acc[2][4][4];
    #pragma unroll
    for (int mi = 0; mi < 2; mi++)
        #pragma unroll
        for (int ni = 0; ni < 4; ni++)
            #pragma unroll
            for (int e = 0; e < 4; e++) acc[mi][ni][e] = 0.f;

    int dd = tid & 15;                  // conv channel within 16-col tile
    int r0 = tid >> 4;                  // 0..15

    for (int kk = 0; kk < KS / BK; kk++) {
        int dbase = z * KS + kk * BK;   // global channel of col 0

        // stage xz rows m0-3 .. m0+127 for 16 channels
        for (int idx = tid; idx < (BM + 3) * 16; idx += 256) {
            int i = idx >> 4, c = idx & 15;
            float v = 0.f;
            if (!(lead_tile && i < 3))
                v = xz[(size_t)(m0 - 3 + i) * (2 * D_INNER) + dbase + c];
            s_xz[i * 16 + c] = v;
        }
        // W tile: rows = 48 outputs (guard to 64), cols = 16 channels
        {
            int r = tid >> 2, c4 = (tid & 3) * 4;
            bool ok = r < DBL_COLS;
            const float* src = ok ? &xpw[(size_t)r * D_INNER + dbase + c4] : xpw;
            cp_async16_z(&Bs[r * LDS + c4], src, ok);
        }
        CP_COMMIT();
        __syncthreads();

        // conv + silu into As
        float w0 = cw[(dbase + dd) * D_CONV + 0];
        float w1 = cw[(dbase + dd) * D_CONV + 1];
        float w2 = cw[(dbase + dd) * D_CONV + 2];
        float w3 = cw[(dbase + dd) * D_CONV + 3];
        float bb = cb[dbase + dd];
        #pragma unroll
        for (int h = 0; h < 8; h++) {
            int r = r0 + 16 * h;
            float v = bb
                + s_xz[(r + 0) * 16 + dd] * w0
                + s_xz[(r + 1) * 16 + dd] * w1
                + s_xz[(r + 2) * 16 + dd] * w2
                + s_xz[(r + 3) * 16 + dd] * w3;
            As[r * LDS + dd] = __float_as_uint(silu_f(v));
        }
        CP_WAIT0();
        __syncthreads();

        #pragma unroll
        for (int ks = 0; ks < BK; ks += 8) {
            uint32_t a[2][4], b[4][2];
            #pragma unroll
            for (int mi = 0; mi < 2; mi++) {
                int rb = wm + mi * 16 + gr;
                a[mi][0] = As[rb * LDS + ks + gc];
                a[mi][1] = As[(rb + 8) * LDS + ks + gc];
                a[mi][2] = As[rb * LDS + ks + gc + 4];
                a[mi][3] = As[(rb + 8) * LDS + ks + gc + 4];
            }
            #pragma unroll
            for (int ni = 0; ni < 4; ni++) {
                int rb = wn + ni * 8 + gr;
                b[ni][0] = Bs[rb * LDS + ks + gc];
                b[ni][1] = Bs[rb * LDS + ks + gc + 4];
            }
            #pragma unroll
            for (int mi = 0; mi < 2; mi++)
                #pragma unroll
                for (int ni = 0; ni < 4; ni++)
                    asm volatile(
                        "mma.sync.aligned.m16n8k8.row.col.f32.tf32.tf32.f32 "
                        "{%0,%1,%2,%3}, {%4,%5,%6,%7}, {%8,%9}, {%0,%1,%2,%3};"
                        : "+f"(acc[mi][ni][0]), "+f"(acc[mi][ni][1]),
                          "+f"(acc[mi][ni][2]), "+f"(acc[mi][ni][3])
                        : "r"(a[mi][0]), "r"(a[mi][1]), "r"(a[mi][2]), "r"(a[mi][3]),
                          "r"(b[ni][0]), "r"(b[ni][1]));
        }
        __syncthreads();
    }

    float* Cp = part + (size_t)z * NTOK * DBL_COLS;
    #pragma unroll
    for (int mi = 0; mi < 2; mi++) {
        #pragma unroll
        for (int ni = 0; ni < 4; ni++) {
            #pragma unroll
            for (int e = 0; e < 4; e++) {
                int row = m0 + wm + mi * 16 + gr + ((e >= 2) ? 8 : 0);
                int col = wn + ni * 8 + gc * 2 + (e & 1);
                if (col < DBL_COLS)
                    Cp[(size_t)row * DBL_COLS + col] = acc[mi][ni][e];
            }
        }
    }
}

// ---------------------------------------------------------------------------
// Reduce x_proj split-K partials
// ---------------------------------------------------------------------------
__global__ void reduce_dbl(const float* __restrict__ part,
                           float* __restrict__ dbl)
{
    int i = blockIdx.x * 256 + threadIdx.x;
    if (i < NTOK * DBL_COLS) {
        float s = part[i];
        #pragma unroll
        for (int zz = 1; zz < XP_SK; zz++)
            s += part[(size_t)zz * NTOK * DBL_COLS + i];
        dbl[i] = s;
    }
}

// ---------------------------------------------------------------------------
// Shared helper: stage xz, compute conv+silu tile + delta tile into smem.
// Block = 256 threads, tile = CLEN x 16 channels (dg group).
// ---------------------------------------------------------------------------
__device__ __forceinline__ void stage_chunk(
    int b, int c, int dg, int tid,
    const float* __restrict__ dbl,
    const float* __restrict__ xz,
    const float* __restrict__ cw,
    const float* __restrict__ cb,
    const float* __restrict__ dpw,
    const float* __restrict__ dpb,
    float* s_dt, float* s_B, float* s_C, float* s_xz,
    float* s_xc, float* s_dl, float* s_pw, bool wantC)
{
    int l0 = c * CLEN;
    const float* dbl_p = dbl + ((size_t)b * SEQLEN + l0) * DBL_COLS;
    const float* xz_p  = xz  + ((size_t)b * SEQLEN + l0) * (2 * D_INNER) + dg * 16;

    for (int idx = tid; idx < CLEN * DBL_COLS; idx += 256) {
        int l = idx / DBL_COLS, cc = idx % DBL_COLS;
        float v = dbl_p[(size_t)l * DBL_COLS + cc];
        if      (cc < 16) s_dt[l * 16 + cc] = v;
        else if (cc < 32) s_B [l * 16 + (cc - 16)] = v;
        else if (wantC)   s_C [l * 16 + (cc - 32)] = v;
    }
    bool lead = (l0 == 0);
    for (int idx = tid; idx < (CLEN + 3) * 16; idx += 256) {
        int i = idx >> 4, cc = idx & 15;
        float v = 0.f;
        if (!(lead && i < 3))
            v = xz_p[(size_t)(i - 3) * (2 * D_INNER) + cc];
        s_xz[i * 16 + cc] = v;
    }
    {
        int rr = tid >> 4, cc = tid & 15;
        s_pw[rr * 17 + cc] = dpw[(size_t)(dg * 16 + rr) * DT_RANK + cc];
    }
    __syncthreads();

    // conv + silu
    {
        int dd = tid & 15, r0 = tid >> 4;
        float w0 = cw[(dg * 16 + dd) * D_CONV + 0];
        float w1 = cw[(dg * 16 + dd) * D_CONV + 1];
        float w2 = cw[(dg * 16 + dd) * D_CONV + 2];
        float w3 = cw[(dg * 16 + dd) * D_CONV + 3];
        float bb = cb[dg * 16 + dd];
        #pragma unroll
        for (int h = 0; h < CLEN / 16; h++) {
            int r = r0 + 16 * h;
            float v = bb
                + s_xz[(r + 0) * 16 + dd] * w0
                + s_xz[(r + 1) * 16 + dd] * w1
                + s_xz[(r + 2) * 16 + dd] * w2
                + s_xz[(r + 3) * 16 + dd] * w3;
            s_xc[r * 16 + dd] = silu_f(v);
        }
    }
    __syncthreads();

    // delta = softplus(dt @ dpw^T + dpb)
    for (int idx = tid; idx < CLEN * 16; idx += 256) {
        int l = idx >> 4, dd2 = idx & 15;
        float acc = dpb[dg * 16 + dd2];
        #pragma unroll
        for (int r = 0; r < 16; r++)
            acc += s_dt[l * 16 + r] * s_pw[dd2 * 17 + r];
        s_dl[l * 16 + dd2] = (acc > 20.f) ? acc : log1pf(__expf(acc));
    }
    __syncthreads();
}

// ---------------------------------------------------------------------------
// Scan part 1: per-chunk a-product + end state.
// ---------------------------------------------------------------------------
__global__ __launch_bounds__(256)
void scan_part1(const float* __restrict__ dbl,
                const float* __restrict__ xz,
                const float* __restrict__ cw,
                const float* __restrict__ cb,
                const float* __restrict__ A_log,
                const float* __restrict__ dpw,
                const float* __restrict__ dpb,
                float* __restrict__ cA,
                float* __restrict__ cH)
{
    __shared__ float s_dt[CLEN * 16], s_B[CLEN * 16];
    __shared__ float s_xz[(CLEN + 3) * 16];
    __shared__ float s_xc[CLEN * 16], s_dl[CLEN * 16];
    __shared__ float s_pw[16 * 17];

    int dg = blockIdx.x & 31;
    int c  = (blockIdx.x >> 5) & (NCHUNK - 1);
    int b  = blockIdx.x >> 10;
    int tid = threadIdx.x;
    int n  = tid & 15;
    int dl = tid >> 4;
    int d  = dg * 16 + dl;

    stage_chunk(b, c, dg, tid, dbl, xz, cw, cb, dpw, dpb,
                s_dt, s_B, nullptr, s_xz, s_xc, s_dl, s_pw, false);

    float Adn = -__expf(A_log[d * D_STATE + n]);
    float h = 0.f, P = 1.f;
    #pragma unroll 8
    for (int l = 0; l < CLEN; l++) {
        float dv = s_dl[l * 16 + dl];
        float a  = __expf(dv * Adn);
        h = a * h + (dv * s_xc[l * 16 + dl]) * s_B[l * 16 + n];
        P *= a;
    }
    size_t o = (((size_t)b * NCHUNK + c) * D_INNER + d) * D_STATE + n;
    cA[o] = P;
    cH[o] = h;
}

// ---------------------------------------------------------------------------
// Scan part 2: sequential chunk combine
// ---------------------------------------------------------------------------
__global__ void scan_part2(const float* __restrict__ cA,
                           const float* __restrict__ cH,
                           float* __restrict__ hs)
{
    int idx = blockIdx.x * blockDim.x + threadIdx.x;
    if (idx >= BATCH * D_INNER * D_STATE) return;
    int b = idx / (D_INNER * D_STATE);
    int r = idx % (D_INNER * D_STATE);
    float h = 0.f;
    #pragma unroll
    for (int c = 0; c < NCHUNK; c++) {
        size_t o = ((size_t)(b * NCHUNK + c)) * (D_INNER * D_STATE) + r;
        hs[o] = h;
        h = cA[o] * h + cH[o];
    }
}

// ---------------------------------------------------------------------------
// Scan part 3: replay + n-reduce + fused gate.
// ---------------------------------------------------------------------------
__global__ __launch_bounds__(256)
void scan_part3(const float* __restrict__ dbl,
                const float* __restrict__ xz,
                const float* __restrict__ cw,
                const float* __restrict__ cb,
                const float* __restrict__ A_log,
                const float* __restrict__ dpw,
                const float* __restrict__ dpb,
                const float* __restrict__ Dp,
                const float* __restrict__ hs,
                float* __restrict__ y)
{
    __shared__ float s_dt[CLEN * 16], s_B[CLEN * 16], s_C[CLEN * 16];
    __shared__ float s_xz[(CLEN + 3) * 16];
    __shared__ float s_xc[CLEN * 16], s_dl[CLEN * 16], s_y[CLEN * 16];
    __shared__ float s_pw[16 * 17];

    int dg = blockIdx.x & 31;
    int c  = (blockIdx.x >> 5) & (NCHUNK - 1);
    int b  = blockIdx.x >> 10;
    int tid = threadIdx.x;
    int n  = tid & 15;
    int dl = tid >> 4;
    int d  = dg * 16 + dl;
    int l0 = c * CLEN;

    stage_chunk(b, c, dg, tid, dbl, xz, cw, cb, dpw, dpb,
                s_dt, s_B, s_C, s_xz, s_xc, s_dl, s_pw, true);

    float Adn = -__expf(A_log[d * D_STATE + n]);
    float h = hs[(((size_t)b * NCHUNK + c) * D_INNER + d) * D_STATE + n];

    #pragma unroll 4
    for (int l = 0; l < CLEN; l++) {
        float dv = s_dl[l * 16 + dl];
        h = __expf(dv * Adn) * h + (dv * s_xc[l * 16 + dl]) * s_B[l * 16 + n];
        float p = h * s_C[l * 16 + n];
        p += __shfl_xor_sync(0xffffffffu, p, 8);
        p += __shfl_xor_sync(0xffffffffu, p, 4);
        p += __shfl_xor_sync(0xffffffffu, p, 2);
        p += __shfl_xor_sync(0xffffffffu, p, 1);
        if (n == 0) s_y[l * 16 + dl] = p;
    }
    __syncthreads();

    const float* z_p = xz + ((size_t)b * SEQLEN + l0) * 2 * D_INNER + D_INNER + dg * 16;
    float*       y_p = y  + ((size_t)b * SEQLEN + l0) * D_INNER + dg * 16;
    for (int idx = tid; idx < CLEN * 16; idx += 256) {
        int l = idx >> 4, dd = idx & 15;
        float z = z_p[(size_t)l * 2 * D_INNER + dd];
        y_p[(size_t)l * D_INNER + dd] =
            (s_y[l * 16 + dd] + s_xc[l * 16 + dd] * Dp[dg * 16 + dd]) * silu_f(z);
    }
}

// ---------------------------------------------------------------------------
// Launcher
// ---------------------------------------------------------------------------
extern "C" void kernel_launch(void* const* d_in, const int* in_sizes, int n_in,
                              void* d_out, int out_size)
{
    const float* x_in = (const float*)d_in[0];
    const float* ln_w = (const float*)d_in[1];
    const float* ln_b = (const float*)d_in[2];
    const float* ipw  = (const float*)d_in[3];
    const float* cw   = (const float*)d_in[4];
    const float* cb   = (const float*)d_in[5];
    const float* xpw  = (const float*)d_in[6];
    const float* dpw  = (const float*)d_in[7];
    const float* dpb  = (const float*)d_in[8];
    const float* alog = (const float*)d_in[9];
    const float* dpar = (const float*)d_in[10];
    const float* opw  = (const float*)d_in[11];
    float* xbuf = (float*)d_out;

    float *p_xz, *p_dbl, *p_part, *p_y, *p_cA, *p_cH, *p_hs;
    float2* p_st;
    cudaGetSymbolAddress((void**)&p_xz,   g_xz);
    cudaGetSymbolAddress((void**)&p_dbl,  g_dbl);
    cudaGetSymbolAddress((void**)&p_part, g_part);
    cudaGetSymbolAddress((void**)&p_y,    g_y);
    cudaGetSymbolAddress((void**)&p_cA,   g_cA);
    cudaGetSymbolAddress((void**)&p_cH,   g_cH);
    cudaGetSymbolAddress((void**)&p_hs,   g_hs);
    cudaGetSymbolAddress((void**)&p_st,   g_stats);

    cudaMemcpyAsync(xbuf, x_in, (size_t)NTOK * D_MODEL * sizeof(float),
                    cudaMemcpyDeviceToDevice);

    const int SCAN_BLOCKS = BATCH * NCHUNK * 32;

    for (int layer = 0; layer < DEPTH; layer++) {
        const float* l_lnw  = ln_w + layer * D_MODEL;
        const float* l_lnb  = ln_b + layer * D_MODEL;
        const float* l_ipw  = ipw  + (size_t)layer * 2 * D_INNER * D_MODEL;
        const float* l_cw   = cw   + (size_t)layer * D_INNER * D_CONV;
        const float* l_cb   = cb   + (size_t)layer * D_INNER;
        const float* l_xpw  = xpw  + (size_t)layer * DBL_COLS * D_INNER;
        const float* l_dpw  = dpw  + (size_t)layer * D_INNER * DT_RANK;
        const float* l_dpb  = dpb  + (size_t)layer * D_INNER;
        const float* l_alog = alog + (size_t)layer * D_INNER * D_STATE;
        const float* l_dpar = dpar + (size_t)layer * D_INNER;
        const float* l_opw  = opw  + (size_t)layer * D_MODEL * D_INNER;

        // 1. LN stats
        ln_stats_kernel<<<NTOK / 8, 256>>>(xbuf, p_st);

        // 2. in_proj with fused LN apply: xz = LN(x) @ ipw^T
        gemm_fused<0, 2, true><<<dim3(16, NTOK / 128), 256>>>(
            xbuf, D_MODEL, l_ipw, D_MODEL, p_xz, 2 * D_INNER,
            2 * D_INNER, D_MODEL, p_st, l_lnw, l_lnb);

        // 3. x_proj with fused conv+silu, split-K=4
        xproj_conv_gemm<<<dim3(1, NTOK / 128, XP_SK), 256>>>(
            p_xz, l_cw, l_cb, l_xpw, p_part);
        reduce_dbl<<<(NTOK * DBL_COLS + 255) / 256, 256>>>(p_part, p_dbl);

        // 4. chunked scan (conv + delta fused) + gate
        scan_part1<<<SCAN_BLOCKS, 256>>>(p_dbl, p_xz, l_cw, l_cb,
                                         l_alog, l_dpw, l_dpb, p_cA, p_cH);
        scan_part2<<<(BATCH * D_INNER * D_STATE + 255) / 256, 256>>>(
            p_cA, p_cH, p_hs);
        scan_part3<<<SCAN_BLOCKS, 256>>>(p_dbl, p_xz, l_cw, l_cb,
                                         l_alog, l_dpw, l_dpb, l_dpar,
                                         p_hs, p_y);

        // 5. out_proj + residual (BM=64 for coverage): xbuf += y @ opw^T
        gemm_fused<2, 1, false><<<dim3(4, NTOK / 64), 256>>>(
            p_y, D_INNER, l_opw, D_INNER, xbuf, D_MODEL,
            D_MODEL, D_INNER, nullptr, nullptr, nullptr);
    }
}

// round 6
// speedup vs baseline: 1.1558x; 1.1558x over previous
#include <cuda_runtime.h>
#include <cuda_bf16.h>
#include <math.h>
#include <stdint.h>

// ---------------------------------------------------------------------------
#define D_MODEL   256
#define DEPTH     2
#define D_INNER   512
#define D_STATE   16
#define D_CONV    4
#define DT_RANK   16
#define BATCH     2
#define SEQLEN    2048
#define NTOK      (BATCH * SEQLEN)          // 4096
#define DBL_COLS  (DT_RANK + 2 * D_STATE)   // 48

#define NCHUNK    32
#define CLEN      (SEQLEN / NCHUNK)         // 64
#define XP_SK     4                          // x_proj split-K

// ---------------------------------------------------------------------------
// Scratch
// ---------------------------------------------------------------------------
__device__ float g_h    [NTOK * D_MODEL];
__device__ float g_xz   [NTOK * 2 * D_INNER];
__device__ float g_xc   [NTOK * D_INNER];
__device__ float g_dbl  [NTOK * DBL_COLS];
__device__ float g_part [XP_SK * NTOK * DBL_COLS];
__device__ float g_y    [NTOK * D_INNER];
__device__ float g_cA   [BATCH * NCHUNK * D_INNER * D_STATE];
__device__ float g_cH   [BATCH * NCHUNK * D_INNER * D_STATE];
__device__ float g_hs   [BATCH * NCHUNK * D_INNER * D_STATE];

// ---------------------------------------------------------------------------
// cp.async helpers
// ---------------------------------------------------------------------------
__device__ __forceinline__ uint32_t smem_u32(const void* p) {
    uint32_t a;
    asm("{.reg .u64 t; cvta.to.shared.u64 t, %1; cvt.u32.u64 %0, t;}"
        : "=r"(a) : "l"(p));
    return a;
}
__device__ __forceinline__ void cp_async16(void* dst, const void* src) {
    asm volatile("cp.async.ca.shared.global [%0], [%1], 16;"
                 :: "r"(smem_u32(dst)), "l"(src));
}
__device__ __forceinline__ void cp_async16_z(void* dst, const void* src, bool ok) {
    int sz = ok ? 16 : 0;
    asm volatile("cp.async.ca.shared.global [%0], [%1], 16, %2;"
                 :: "r"(smem_u32(dst)), "l"(src), "r"(sz));
}
#define CP_COMMIT() asm volatile("cp.async.commit_group;")
#define CP_WAIT0()  asm volatile("cp.async.wait_group 0;")

// ---------------------------------------------------------------------------
// LayerNorm: one block per token, 256 threads
// ---------------------------------------------------------------------------
__global__ void ln_kernel(const float* __restrict__ x,
                          const float* __restrict__ w,
                          const float* __restrict__ b,
                          float* __restrict__ out)
{
    __shared__ float s_sum[8], s_sq[8];
    int t = blockIdx.x;
    int d = threadIdx.x;
    float v = x[t * D_MODEL + d];

    float s = v, q = v * v;
    #pragma unroll
    for (int o = 16; o > 0; o >>= 1) {
        s += __shfl_xor_sync(0xffffffffu, s, o);
        q += __shfl_xor_sync(0xffffffffu, q, o);
    }
    int warp = threadIdx.x >> 5;
    if ((threadIdx.x & 31) == 0) { s_sum[warp] = s; s_sq[warp] = q; }
    __syncthreads();
    if (threadIdx.x < 8) { s = s_sum[threadIdx.x]; q = s_sq[threadIdx.x]; }
    else                 { s = 0.f; q = 0.f; }
    if (warp == 0) {
        #pragma unroll
        for (int o = 4; o > 0; o >>= 1) {
            s += __shfl_xor_sync(0xffffffffu, s, o);
            q += __shfl_xor_sync(0xffffffffu, q, o);
        }
        if (threadIdx.x == 0) { s_sum[0] = s; s_sq[0] = q; }
    }
    __syncthreads();
    float mu  = s_sum[0] * (1.f / D_MODEL);
    float var = s_sq[0] * (1.f / D_MODEL) - mu * mu;
    float inv = rsqrtf(var + 1e-5f);
    out[t * D_MODEL + d] = (v - mu) * inv * w[d] + b[d];
}

// ---------------------------------------------------------------------------
// tf32 tensor-core GEMM, cp.async double-buffered, wide warp tile.
// C[M,N] = A[M,K] @ W[N,K]^T.  MODE 0: store | MODE 2: C += acc.
// BM=128, BN=16*NI (NI=4 -> 64, NI=8 -> 128). 256 threads = 8 warps (4Mx2N),
// warp tile 32 x (8*NI). blockIdx.z = split-K slice (A += z*K, C += z*csplit).
// ---------------------------------------------------------------------------
template <int MODE, int NI>
__global__ __launch_bounds__(256)
void gemm_tf32(const float* __restrict__ A, int lda,
               const float* __restrict__ W, int ldw,
               float*       __restrict__ C, int ldc,
               int N, int K, size_t csplit)
{
    const int BM = 128, BN = 16 * NI, BK = 16, LDS = 20;
    __shared__ uint32_t As[2][BM * LDS];
    __shared__ uint32_t Bs[2][BN * LDS];

    A += (size_t)blockIdx.z * K;
    C += (size_t)blockIdx.z * csplit;

    int tid  = threadIdx.x;
    int lane = tid & 31;
    int warp = tid >> 5;
    int m0 = blockIdx.y * BM;
    int n0 = blockIdx.x * BN;
    int wm = (warp >> 1) * 32;
    int wn = (warp & 1) * 8 * NI;
    int gr = lane >> 2;
    int gc = lane & 3;

    float acc[2][NI][4];
    #pragma unroll
    for (int mi = 0; mi < 2; mi++)
        #pragma unroll
        for (int ni = 0; ni < NI; ni++)
            #pragma unroll
            for (int e = 0; e < 4; e++) acc[mi][ni][e] = 0.f;

    int lrow = tid >> 2;           // 0..63
    int lcol = (tid & 3) * 4;      // 0,4,8,12

    auto issue = [&](int k0, int buf) {
        #pragma unroll
        for (int h = 0; h < 2; h++) {
            int r = lrow + h * 64;
            cp_async16(&As[buf][r * LDS + lcol],
                       &A[(size_t)(m0 + r) * lda + k0 + lcol]);
        }
        #pragma unroll
        for (int h = 0; h < NI / 4; h++) {
            int r = lrow + h * 64;
            bool ok = (n0 + r) < N;
            const float* src = ok ? &W[(size_t)(n0 + r) * ldw + k0 + lcol] : W;
            cp_async16_z(&Bs[buf][r * LDS + lcol], src, ok);
        }
    };

    int nk = K / BK;
    issue(0, 0);
    CP_COMMIT();

    for (int i = 0; i < nk; i++) {
        CP_WAIT0();
        __syncthreads();
        if (i + 1 < nk) { issue((i + 1) * BK, (i + 1) & 1); CP_COMMIT(); }
        int buf = i & 1;

        #pragma unroll
        for (int ks = 0; ks < BK; ks += 8) {
            uint32_t a[2][4], b[NI][2];
            #pragma unroll
            for (int mi = 0; mi < 2; mi++) {
                int rb = wm + mi * 16 + gr;
                a[mi][0] = As[buf][rb * LDS + ks + gc];
                a[mi][1] = As[buf][(rb + 8) * LDS + ks + gc];
                a[mi][2] = As[buf][rb * LDS + ks + gc + 4];
                a[mi][3] = As[buf][(rb + 8) * LDS + ks + gc + 4];
            }
            #pragma unroll
            for (int ni = 0; ni < NI; ni++) {
                int rb = wn + ni * 8 + gr;
                b[ni][0] = Bs[buf][rb * LDS + ks + gc];
                b[ni][1] = Bs[buf][rb * LDS + ks + gc + 4];
            }
            #pragma unroll
            for (int mi = 0; mi < 2; mi++)
                #pragma unroll
                for (int ni = 0; ni < NI; ni++)
                    asm volatile(
                        "mma.sync.aligned.m16n8k8.row.col.f32.tf32.tf32.f32 "
                        "{%0,%1,%2,%3}, {%4,%5,%6,%7}, {%8,%9}, {%0,%1,%2,%3};"
                        : "+f"(acc[mi][ni][0]), "+f"(acc[mi][ni][1]),
                          "+f"(acc[mi][ni][2]), "+f"(acc[mi][ni][3])
                        : "r"(a[mi][0]), "r"(a[mi][1]), "r"(a[mi][2]), "r"(a[mi][3]),
                          "r"(b[ni][0]), "r"(b[ni][1]));
        }
    }

    // Epilogue: float2 stores (cols (c, c+1) are acc[e=0],[e=1] / [2],[3])
    #pragma unroll
    for (int mi = 0; mi < 2; mi++) {
        #pragma unroll
        for (int ni = 0; ni < NI; ni++) {
            int col = n0 + wn + ni * 8 + gc * 2;
            if (col < N) {
                #pragma unroll
                for (int half = 0; half < 2; half++) {
                    int row = m0 + wm + mi * 16 + gr + half * 8;
                    float2 v = make_float2(acc[mi][ni][half * 2],
                                           acc[mi][ni][half * 2 + 1]);
                    float2* cp = (float2*)&C[(size_t)row * ldc + col];
                    if (MODE == 2) {
                        float2 o = *cp;
                        v.x += o.x; v.y += o.y;
                    }
                    *cp = v;
                }
            }
        }
    }
}

// ---------------------------------------------------------------------------
// Reduce x_proj split-K partials
// ---------------------------------------------------------------------------
__global__ void reduce_dbl(const float* __restrict__ part,
                           float* __restrict__ dbl)
{
    int i = blockIdx.x * 256 + threadIdx.x;
    if (i < NTOK * DBL_COLS) {
        float s = part[i];
        #pragma unroll
        for (int z = 1; z < XP_SK; z++)
            s += part[(size_t)z * NTOK * DBL_COLS + i];
        dbl[i] = s;
    }
}

// ---------------------------------------------------------------------------
// Depthwise causal conv (D_CONV=4) + SiLU
// ---------------------------------------------------------------------------
__global__ void conv_silu_kernel(const float* __restrict__ xz,
                                 const float* __restrict__ cw,
                                 const float* __restrict__ cb,
                                 float* __restrict__ xc)
{
    int idx = blockIdx.x * blockDim.x + threadIdx.x;
    if (idx >= NTOK * D_INNER) return;
    int d = idx & (D_INNER - 1);
    int t = idx >> 9;
    int l = t & (SEQLEN - 1);

    float acc = cb[d];
    #pragma unroll
    for (int k = 0; k < D_CONV; k++) {
        int ll = l - (D_CONV - 1) + k;
        if (ll >= 0)
            acc += xz[(size_t)(t - (D_CONV - 1) + k) * (2 * D_INNER) + d] * cw[d * D_CONV + k];
    }
    float sg = 1.f / (1.f + __expf(-acc));
    xc[idx] = acc * sg;
}

// ---------------------------------------------------------------------------
// Scan part 1: per-chunk a-product + end state, delta fused, smem-staged.
// Grid: BATCH*NCHUNK*32, block 256 = 16 d x 16 n.
// ---------------------------------------------------------------------------
__global__ __launch_bounds__(256)
void scan_part1(const float* __restrict__ dbl,
                const float* __restrict__ xc,
                const float* __restrict__ A_log,
                const float* __restrict__ dpw,
                const float* __restrict__ dpb,
                float* __restrict__ cA,
                float* __restrict__ cH)
{
    __shared__ float s_dt[CLEN * 16];
    __shared__ float s_B [CLEN * 16];
    __shared__ float s_xc[CLEN * 16];
    __shared__ float s_dl[CLEN * 16];
    __shared__ float s_pw[16 * 17];

    int dg = blockIdx.x & 31;
    int c  = (blockIdx.x >> 5) & (NCHUNK - 1);
    int b  = blockIdx.x >> 10;
    int tid = threadIdx.x;
    int n  = tid & 15;
    int dl = tid >> 4;
    int d  = dg * 16 + dl;
    int l0 = c * CLEN;

    const float* dbl_p = dbl + ((size_t)b * SEQLEN + l0) * DBL_COLS;
    const float* xc_p  = xc  + ((size_t)b * SEQLEN + l0) * D_INNER + dg * 16;

    for (int idx = tid; idx < CLEN * 32; idx += 256) {
        int l = idx >> 5, cc = idx & 31;
        float v = dbl_p[(size_t)l * DBL_COLS + cc];
        if (cc < 16) s_dt[l * 16 + cc] = v;
        else         s_B [l * 16 + (cc - 16)] = v;
    }
    for (int idx = tid; idx < CLEN * 16; idx += 256) {
        int l = idx >> 4, dd = idx & 15;
        s_xc[l * 16 + dd] = xc_p[(size_t)l * D_INNER + dd];
    }
    {
        int rr = tid >> 4, cc = tid & 15;
        s_pw[rr * 17 + cc] = dpw[(size_t)(dg * 16 + rr) * DT_RANK + cc];
    }
    __syncthreads();

    for (int idx = tid; idx < CLEN * 16; idx += 256) {
        int l = idx >> 4, dd = idx & 15;
        float acc = dpb[dg * 16 + dd];
        #pragma unroll
        for (int r = 0; r < 16; r++)
            acc += s_dt[l * 16 + r] * s_pw[dd * 17 + r];
        s_dl[l * 16 + dd] = (acc > 20.f) ? acc : log1pf(__expf(acc));
    }
    __syncthreads();

    float Adn = -__expf(A_log[d * D_STATE + n]);
    float h = 0.f, P = 1.f;
    #pragma unroll 8
    for (int l = 0; l < CLEN; l++) {
        float dv = s_dl[l * 16 + dl];
        float a  = __expf(dv * Adn);
        h = a * h + (dv * s_xc[l * 16 + dl]) * s_B[l * 16 + n];
        P *= a;
    }
    size_t o = (((size_t)b * NCHUNK + c) * D_INNER + d) * D_STATE + n;
    cA[o] = P;
    cH[o] = h;
}

// ---------------------------------------------------------------------------
// Scan part 2: sequential chunk combine
// ---------------------------------------------------------------------------
__global__ void scan_part2(const float* __restrict__ cA,
                           const float* __restrict__ cH,
                           float* __restrict__ hs)
{
    int idx = blockIdx.x * blockDim.x + threadIdx.x;
    if (idx >= BATCH * D_INNER * D_STATE) return;
    int b = idx / (D_INNER * D_STATE);
    int r = idx % (D_INNER * D_STATE);
    float h = 0.f;
    #pragma unroll
    for (int c = 0; c < NCHUNK; c++) {
        size_t o = ((size_t)(b * NCHUNK + c)) * (D_INNER * D_STATE) + r;
        hs[o] = h;
        h = cA[o] * h + cH[o];
    }
}

// ---------------------------------------------------------------------------
// Scan part 3: replay with true start state, reduce over n, fused gate.
// ---------------------------------------------------------------------------
__global__ __launch_bounds__(256)
void scan_part3(const float* __restrict__ dbl,
                const float* __restrict__ xc,
                const float* __restrict__ xz,
                const float* __restrict__ A_log,
                const float* __restrict__ dpw,
                const float* __restrict__ dpb,
                const float* __restrict__ Dp,
                const float* __restrict__ hs,
                float* __restrict__ y)
{
    __shared__ float s_dt[CLEN * 16];
    __shared__ float s_B [CLEN * 16];
    __shared__ float s_C [CLEN * 16];
    __shared__ float s_xc[CLEN * 16];
    __shared__ float s_dl[CLEN * 16];
    __shared__ float s_y [CLEN * 16];
    __shared__ float s_pw[16 * 17];

    int dg = blockIdx.x & 31;
    int c  = (blockIdx.x >> 5) & (NCHUNK - 1);
    int b  = blockIdx.x >> 10;
    int tid = threadIdx.x;
    int n  = tid & 15;
    int dl = tid >> 4;
    int d  = dg * 16 + dl;
    int l0 = c * CLEN;

    const float* dbl_p = dbl + ((size_t)b * SEQLEN + l0) * DBL_COLS;
    const float* xc_p  = xc  + ((size_t)b * SEQLEN + l0) * D_INNER + dg * 16;
    const float* z_p   = xz  + ((size_t)b * SEQLEN + l0) * 2 * D_INNER + D_INNER + dg * 16;
    float*       y_p   = y   + ((size_t)b * SEQLEN + l0) * D_INNER + dg * 16;

    for (int idx = tid; idx < CLEN * DBL_COLS; idx += 256) {
        int l = idx / DBL_COLS, cc = idx % DBL_COLS;
        float v = dbl_p[(size_t)l * DBL_COLS + cc];
        if      (cc < 16) s_dt[l * 16 + cc] = v;
        else if (cc < 32) s_B [l * 16 + (cc - 16)] = v;
        else              s_C [l * 16 + (cc - 32)] = v;
    }
    for (int idx = tid; idx < CLEN * 16; idx += 256) {
        int l = idx >> 4, dd = idx & 15;
        s_xc[l * 16 + dd] = xc_p[(size_t)l * D_INNER + dd];
    }
    {
        int rr = tid >> 4, cc = tid & 15;
        s_pw[rr * 17 + cc] = dpw[(size_t)(dg * 16 + rr) * DT_RANK + cc];
    }
    __syncthreads();

    for (int idx = tid; idx < CLEN * 16; idx += 256) {
        int l = idx >> 4, dd = idx & 15;
        float acc = dpb[dg * 16 + dd];
        #pragma unroll
        for (int r = 0; r < 16; r++)
            acc += s_dt[l * 16 + r] * s_pw[dd * 17 + r];
        s_dl[l * 16 + dd] = (acc > 20.f) ? acc : log1pf(__expf(acc));
    }
    __syncthreads();

    float Adn = -__expf(A_log[d * D_STATE + n]);
    float h = hs[(((size_t)b * NCHUNK + c) * D_INNER + d) * D_STATE + n];

    #pragma unroll 4
    for (int l = 0; l < CLEN; l++) {
        float dv = s_dl[l * 16 + dl];
        h = __expf(dv * Adn) * h + (dv * s_xc[l * 16 + dl]) * s_B[l * 16 + n];
        float p = h * s_C[l * 16 + n];
        p += __shfl_xor_sync(0xffffffffu, p, 8);
        p += __shfl_xor_sync(0xffffffffu, p, 4);
        p += __shfl_xor_sync(0xffffffffu, p, 2);
        p += __shfl_xor_sync(0xffffffffu, p, 1);
        if (n == 0) s_y[l * 16 + dl] = p;
    }
    __syncthreads();

    for (int idx = tid; idx < CLEN * 16; idx += 256) {
        int l = idx >> 4, dd = idx & 15;
        float z = z_p[(size_t)l * 2 * D_INNER + dd];
        float sz = z / (1.f + __expf(-z));
        y_p[(size_t)l * D_INNER + dd] =
            (s_y[l * 16 + dd] + s_xc[l * 16 + dd] * Dp[dg * 16 + dd]) * sz;
    }
}

// ---------------------------------------------------------------------------
// Launcher
// ---------------------------------------------------------------------------
extern "C" void kernel_launch(void* const* d_in, const int* in_sizes, int n_in,
                              void* d_out, int out_size)
{
    const float* x_in = (const float*)d_in[0];
    const float* ln_w = (const float*)d_in[1];
    const float* ln_b = (const float*)d_in[2];
    const float* ipw  = (const float*)d_in[3];
    const float* cw   = (const float*)d_in[4];
    const float* cb   = (const float*)d_in[5];
    const float* xpw  = (const float*)d_in[6];
    const float* dpw  = (const float*)d_in[7];
    const float* dpb  = (const float*)d_in[8];
    const float* alog = (const float*)d_in[9];
    const float* dpar = (const float*)d_in[10];
    const float* opw  = (const float*)d_in[11];
    float* xbuf = (float*)d_out;

    float *p_h, *p_xz, *p_xc, *p_dbl, *p_part, *p_y, *p_cA, *p_cH, *p_hs;
    cudaGetSymbolAddress((void**)&p_h,    g_h);
    cudaGetSymbolAddress((void**)&p_xz,   g_xz);
    cudaGetSymbolAddress((void**)&p_xc,   g_xc);
    cudaGetSymbolAddress((void**)&p_dbl,  g_dbl);
    cudaGetSymbolAddress((void**)&p_part, g_part);
    cudaGetSymbolAddress((void**)&p_y,    g_y);
    cudaGetSymbolAddress((void**)&p_cA,   g_cA);
    cudaGetSymbolAddress((void**)&p_cH,   g_cH);
    cudaGetSymbolAddress((void**)&p_hs,   g_hs);

    cudaMemcpyAsync(xbuf, x_in, (size_t)NTOK * D_MODEL * sizeof(float),
                    cudaMemcpyDeviceToDevice);

    const int EW_THREADS = 256;
    const int EW_BLOCKS  = (NTOK * D_INNER + EW_THREADS - 1) / EW_THREADS;
    const int SCAN_BLOCKS = BATCH * NCHUNK * 32;

    for (int layer = 0; layer < DEPTH; layer++) {
        const float* l_lnw  = ln_w + layer * D_MODEL;
        const float* l_lnb  = ln_b + layer * D_MODEL;
        const float* l_ipw  = ipw  + (size_t)layer * 2 * D_INNER * D_MODEL;
        const float* l_cw   = cw   + (size_t)layer * D_INNER * D_CONV;
        const float* l_cb   = cb   + (size_t)layer * D_INNER;
        const float* l_xpw  = xpw  + (size_t)layer * DBL_COLS * D_INNER;
        const float* l_dpw  = dpw  + (size_t)layer * D_INNER * DT_RANK;
        const float* l_dpb  = dpb  + (size_t)layer * D_INNER;
        const float* l_alog = alog + (size_t)layer * D_INNER * D_STATE;
        const float* l_dpar = dpar + (size_t)layer * D_INNER;
        const float* l_opw  = opw  + (size_t)layer * D_MODEL * D_INNER;

        // 1. LayerNorm
        ln_kernel<<<NTOK, D_MODEL>>>(xbuf, l_lnw, l_lnb, p_h);

        // 2. in_proj: [4096,1024] = h @ ipw^T   (BN=128 wide tile)
        gemm_tf32<0, 8><<<dim3(8, NTOK / 128, 1), 256>>>(
            p_h, D_MODEL, l_ipw, D_MODEL, p_xz, 2 * D_INNER,
            2 * D_INNER, D_MODEL, 0);

        // 3. conv + silu
        conv_silu_kernel<<<EW_BLOCKS, EW_THREADS>>>(p_xz, l_cw, l_cb, p_xc);

        // 4. x_proj split-K=4: partials, then reduce
        gemm_tf32<0, 4><<<dim3(1, NTOK / 128, XP_SK), 256>>>(
            p_xc, D_INNER, l_xpw, D_INNER, p_part, DBL_COLS,
            DBL_COLS, D_INNER / XP_SK, (size_t)NTOK * DBL_COLS);
        reduce_dbl<<<(NTOK * DBL_COLS + 255) / 256, 256>>>(p_part, p_dbl);

        // 5. chunked scan (delta fused) + gate
        scan_part1<<<SCAN_BLOCKS, 256>>>(p_dbl, p_xc, l_alog, l_dpw, l_dpb,
                                         p_cA, p_cH);
        scan_part2<<<(BATCH * D_INNER * D_STATE + 255) / 256, 256>>>(
            p_cA, p_cH, p_hs);
        scan_part3<<<SCAN_BLOCKS, 256>>>(p_dbl, p_xc, p_xz, l_alog, l_dpw,
                                         l_dpb, l_dpar, p_hs, p_y);

        // 6. out_proj + residual
        gemm_tf32<2, 4><<<dim3(4, NTOK / 128, 1), 256>>>(
            p_y, D_INNER, l_opw, D_INNER, xbuf, D_MODEL,
            D_MODEL, D_INNER, 0);
    }
}

// round 7
// speedup vs baseline: 1.1893x; 1.0290x over previous
#include <cuda_runtime.h>
#include <cuda_bf16.h>
#include <math.h>
#include <stdint.h>

// ---------------------------------------------------------------------------
#define D_MODEL   256
#define DEPTH     2
#define D_INNER   512
#define D_STATE   16
#define D_CONV    4
#define DT_RANK   16
#define BATCH     2
#define SEQLEN    2048
#define NTOK      (BATCH * SEQLEN)          // 4096
#define DBL_COLS  (DT_RANK + 2 * D_STATE)   // 48

#define NCHUNK    32
#define CLEN      (SEQLEN / NCHUNK)         // 64
#define XP_SK     4                          // x_proj split-K

// PDL: wait for upstream kernel (no-op when no PDL dependency exists)
#define GRID_WAIT() asm volatile("griddepcontrol.wait;" ::: "memory")

// ---------------------------------------------------------------------------
// Scratch
// ---------------------------------------------------------------------------
__device__ float g_h    [NTOK * D_MODEL];
__device__ float g_xz   [NTOK * 2 * D_INNER];
__device__ float g_xc   [NTOK * D_INNER];
__device__ float g_dbl  [NTOK * DBL_COLS];
__device__ float g_part [XP_SK * NTOK * DBL_COLS];
__device__ float g_y    [NTOK * D_INNER];
__device__ float g_cA   [BATCH * NCHUNK * D_INNER * D_STATE];
__device__ float g_cH   [BATCH * NCHUNK * D_INNER * D_STATE];
__device__ float g_hs   [BATCH * NCHUNK * D_INNER * D_STATE];

// ---------------------------------------------------------------------------
// cp.async helpers
// ---------------------------------------------------------------------------
__device__ __forceinline__ uint32_t smem_u32(const void* p) {
    uint32_t a;
    asm("{.reg .u64 t; cvta.to.shared.u64 t, %1; cvt.u32.u64 %0, t;}"
        : "=r"(a) : "l"(p));
    return a;
}
__device__ __forceinline__ void cp_async16(void* dst, const void* src) {
    asm volatile("cp.async.ca.shared.global [%0], [%1], 16;"
                 :: "r"(smem_u32(dst)), "l"(src));
}
__device__ __forceinline__ void cp_async16_z(void* dst, const void* src, bool ok) {
    int sz = ok ? 16 : 0;
    asm volatile("cp.async.ca.shared.global [%0], [%1], 16, %2;"
                 :: "r"(smem_u32(dst)), "l"(src), "r"(sz));
}
#define CP_COMMIT() asm volatile("cp.async.commit_group;")
#define CP_WAIT0()  asm volatile("cp.async.wait_group 0;")

// ---------------------------------------------------------------------------
// LayerNorm: one block per token, 256 threads
// ---------------------------------------------------------------------------
__global__ void ln_kernel(const float* __restrict__ x,
                          const float* __restrict__ w,
                          const float* __restrict__ b,
                          float* __restrict__ out)
{
    GRID_WAIT();
    __shared__ float s_sum[8], s_sq[8];
    int t = blockIdx.x;
    int d = threadIdx.x;
    float v = x[t * D_MODEL + d];

    float s = v, q = v * v;
    #pragma unroll
    for (int o = 16; o > 0; o >>= 1) {
        s += __shfl_xor_sync(0xffffffffu, s, o);
        q += __shfl_xor_sync(0xffffffffu, q, o);
    }
    int warp = threadIdx.x >> 5;
    if ((threadIdx.x & 31) == 0) { s_sum[warp] = s; s_sq[warp] = q; }
    __syncthreads();
    if (threadIdx.x < 8) { s = s_sum[threadIdx.x]; q = s_sq[threadIdx.x]; }
    else                 { s = 0.f; q = 0.f; }
    if (warp == 0) {
        #pragma unroll
        for (int o = 4; o > 0; o >>= 1) {
            s += __shfl_xor_sync(0xffffffffu, s, o);
            q += __shfl_xor_sync(0xffffffffu, q, o);
        }
        if (threadIdx.x == 0) { s_sum[0] = s; s_sq[0] = q; }
    }
    __syncthreads();
    float mu  = s_sum[0] * (1.f / D_MODEL);
    float var = s_sq[0] * (1.f / D_MODEL) - mu * mu;
    float inv = rsqrtf(var + 1e-5f);
    out[t * D_MODEL + d] = (v - mu) * inv * w[d] + b[d];
}

// ---------------------------------------------------------------------------
// tf32 tensor-core GEMM, cp.async double-buffered, wide warp tile.
// C[M,N] = A[M,K] @ W[N,K]^T.  MODE 0: store | MODE 2: C += acc.
// BM=128, BN=16*NI. 256 threads = 8 warps (4Mx2N), warp tile 32 x (8*NI).
// blockIdx.z = split-K slice (A += z*K, C += z*csplit).
// ---------------------------------------------------------------------------
template <int MODE, int NI>
__global__ __launch_bounds__(256)
void gemm_tf32(const float* __restrict__ A, int lda,
               const float* __restrict__ W, int ldw,
               float*       __restrict__ C, int ldc,
               int N, int K, size_t csplit)
{
    GRID_WAIT();
    const int BM = 128, BN = 16 * NI, BK = 16, LDS = 20;
    __shared__ uint32_t As[2][BM * LDS];
    __shared__ uint32_t Bs[2][BN * LDS];

    A += (size_t)blockIdx.z * K;
    C += (size_t)blockIdx.z * csplit;

    int tid  = threadIdx.x;
    int lane = tid & 31;
    int warp = tid >> 5;
    int m0 = blockIdx.y * BM;
    int n0 = blockIdx.x * BN;
    int wm = (warp >> 1) * 32;
    int wn = (warp & 1) * 8 * NI;
    int gr = lane >> 2;
    int gc = lane & 3;

    float acc[2][NI][4];
    #pragma unroll
    for (int mi = 0; mi < 2; mi++)
        #pragma unroll
        for (int ni = 0; ni < NI; ni++)
            #pragma unroll
            for (int e = 0; e < 4; e++) acc[mi][ni][e] = 0.f;

    int lrow = tid >> 2;           // 0..63
    int lcol = (tid & 3) * 4;      // 0,4,8,12

    auto issue = [&](int k0, int buf) {
        #pragma unroll
        for (int h = 0; h < 2; h++) {
            int r = lrow + h * 64;
            cp_async16(&As[buf][r * LDS + lcol],
                       &A[(size_t)(m0 + r) * lda + k0 + lcol]);
        }
        #pragma unroll
        for (int h = 0; h < NI / 4; h++) {
            int r = lrow + h * 64;
            bool ok = (n0 + r) < N;
            const float* src = ok ? &W[(size_t)(n0 + r) * ldw + k0 + lcol] : W;
            cp_async16_z(&Bs[buf][r * LDS + lcol], src, ok);
        }
    };

    int nk = K / BK;
    issue(0, 0);
    CP_COMMIT();

    for (int i = 0; i < nk; i++) {
        CP_WAIT0();
        __syncthreads();
        if (i + 1 < nk) { issue((i + 1) * BK, (i + 1) & 1); CP_COMMIT(); }
        int buf = i & 1;

        #pragma unroll
        for (int ks = 0; ks < BK; ks += 8) {
            uint32_t a[2][4], b[NI][2];
            #pragma unroll
            for (int mi = 0; mi < 2; mi++) {
                int rb = wm + mi * 16 + gr;
                a[mi][0] = As[buf][rb * LDS + ks + gc];
                a[mi][1] = As[buf][(rb + 8) * LDS + ks + gc];
                a[mi][2] = As[buf][rb * LDS + ks + gc + 4];
                a[mi][3] = As[buf][(rb + 8) * LDS + ks + gc + 4];
            }
            #pragma unroll
            for (int ni = 0; ni < NI; ni++) {
                int rb = wn + ni * 8 + gr;
                b[ni][0] = Bs[buf][rb * LDS + ks + gc];
                b[ni][1] = Bs[buf][rb * LDS + ks + gc + 4];
            }
            #pragma unroll
            for (int mi = 0; mi < 2; mi++)
                #pragma unroll
                for (int ni = 0; ni < NI; ni++)
                    asm volatile(
                        "mma.sync.aligned.m16n8k8.row.col.f32.tf32.tf32.f32 "
                        "{%0,%1,%2,%3}, {%4,%5,%6,%7}, {%8,%9}, {%0,%1,%2,%3};"
                        : "+f"(acc[mi][ni][0]), "+f"(acc[mi][ni][1]),
                          "+f"(acc[mi][ni][2]), "+f"(acc[mi][ni][3])
                        : "r"(a[mi][0]), "r"(a[mi][1]), "r"(a[mi][2]), "r"(a[mi][3]),
                          "r"(b[ni][0]), "r"(b[ni][1]));
        }
    }

    // Epilogue: float2 stores
    #pragma unroll
    for (int mi = 0; mi < 2; mi++) {
        #pragma unroll
        for (int ni = 0; ni < NI; ni++) {
            int col = n0 + wn + ni * 8 + gc * 2;
            if (col < N) {
                #pragma unroll
                for (int half = 0; half < 2; half++) {
                    int row = m0 + wm + mi * 16 + gr + half * 8;
                    float2 v = make_float2(acc[mi][ni][half * 2],
                                           acc[mi][ni][half * 2 + 1]);
                    float2* cp = (float2*)&C[(size_t)row * ldc + col];
                    if (MODE == 2) {
                        float2 o = *cp;
                        v.x += o.x; v.y += o.y;
                    }
                    *cp = v;
                }
            }
        }
    }
}

// ---------------------------------------------------------------------------
// Reduce x_proj split-K partials
// ---------------------------------------------------------------------------
__global__ void reduce_dbl(const float* __restrict__ part,
                           float* __restrict__ dbl)
{
    GRID_WAIT();
    int i = blockIdx.x * 256 + threadIdx.x;
    if (i < NTOK * DBL_COLS) {
        float s = part[i];
        #pragma unroll
        for (int z = 1; z < XP_SK; z++)
            s += part[(size_t)z * NTOK * DBL_COLS + i];
        dbl[i] = s;
    }
}

// ---------------------------------------------------------------------------
// Depthwise causal conv (D_CONV=4) + SiLU
// ---------------------------------------------------------------------------
__global__ void conv_silu_kernel(const float* __restrict__ xz,
                                 const float* __restrict__ cw,
                                 const float* __restrict__ cb,
                                 float* __restrict__ xc)
{
    GRID_WAIT();
    int idx = blockIdx.x * blockDim.x + threadIdx.x;
    if (idx >= NTOK * D_INNER) return;
    int d = idx & (D_INNER - 1);
    int t = idx >> 9;
    int l = t & (SEQLEN - 1);

    float acc = cb[d];
    #pragma unroll
    for (int k = 0; k < D_CONV; k++) {
        int ll = l - (D_CONV - 1) + k;
        if (ll >= 0)
            acc += xz[(size_t)(t - (D_CONV - 1) + k) * (2 * D_INNER) + d] * cw[d * D_CONV + k];
    }
    float sg = 1.f / (1.f + __expf(-acc));
    xc[idx] = acc * sg;
}

// ---------------------------------------------------------------------------
// Scan part 1: per-chunk a-product + end state, delta fused, smem-staged.
// ---------------------------------------------------------------------------
__global__ __launch_bounds__(256)
void scan_part1(const float* __restrict__ dbl,
                const float* __restrict__ xc,
                const float* __restrict__ A_log,
                const float* __restrict__ dpw,
                const float* __restrict__ dpb,
                float* __restrict__ cA,
                float* __restrict__ cH)
{
    GRID_WAIT();
    __shared__ float s_dt[CLEN * 16];
    __shared__ float s_B [CLEN * 16];
    __shared__ float s_xc[CLEN * 16];
    __shared__ float s_dl[CLEN * 16];
    __shared__ float s_pw[16 * 17];

    int dg = blockIdx.x & 31;
    int c  = (blockIdx.x >> 5) & (NCHUNK - 1);
    int b  = blockIdx.x >> 10;
    int tid = threadIdx.x;
    int n  = tid & 15;
    int dl = tid >> 4;
    int d  = dg * 16 + dl;
    int l0 = c * CLEN;

    const float* dbl_p = dbl + ((size_t)b * SEQLEN + l0) * DBL_COLS;
    const float* xc_p  = xc  + ((size_t)b * SEQLEN + l0) * D_INNER + dg * 16;

    for (int idx = tid; idx < CLEN * 32; idx += 256) {
        int l = idx >> 5, cc = idx & 31;
        float v = dbl_p[(size_t)l * DBL_COLS + cc];
        if (cc < 16) s_dt[l * 16 + cc] = v;
        else         s_B [l * 16 + (cc - 16)] = v;
    }
    for (int idx = tid; idx < CLEN * 16; idx += 256) {
        int l = idx >> 4, dd = idx & 15;
        s_xc[l * 16 + dd] = xc_p[(size_t)l * D_INNER + dd];
    }
    {
        int rr = tid >> 4, cc = tid & 15;
        s_pw[rr * 17 + cc] = dpw[(size_t)(dg * 16 + rr) * DT_RANK + cc];
    }
    __syncthreads();

    for (int idx = tid; idx < CLEN * 16; idx += 256) {
        int l = idx >> 4, dd = idx & 15;
        float acc = dpb[dg * 16 + dd];
        #pragma unroll
        for (int r = 0; r < 16; r++)
            acc += s_dt[l * 16 + r] * s_pw[dd * 17 + r];
        s_dl[l * 16 + dd] = (acc > 20.f) ? acc : log1pf(__expf(acc));
    }
    __syncthreads();

    float Adn = -__expf(A_log[d * D_STATE + n]);
    float h = 0.f, P = 1.f;
    #pragma unroll 8
    for (int l = 0; l < CLEN; l++) {
        float dv = s_dl[l * 16 + dl];
        float a  = __expf(dv * Adn);
        h = a * h + (dv * s_xc[l * 16 + dl]) * s_B[l * 16 + n];
        P *= a;
    }
    size_t o = (((size_t)b * NCHUNK + c) * D_INNER + d) * D_STATE + n;
    cA[o] = P;
    cH[o] = h;
}

// ---------------------------------------------------------------------------
// Scan part 2: sequential chunk combine
// ---------------------------------------------------------------------------
__global__ void scan_part2(const float* __restrict__ cA,
                           const float* __restrict__ cH,
                           float* __restrict__ hs)
{
    GRID_WAIT();
    int idx = blockIdx.x * blockDim.x + threadIdx.x;
    if (idx >= BATCH * D_INNER * D_STATE) return;
    int b = idx / (D_INNER * D_STATE);
    int r = idx % (D_INNER * D_STATE);
    float h = 0.f;
    #pragma unroll
    for (int c = 0; c < NCHUNK; c++) {
        size_t o = ((size_t)(b * NCHUNK + c)) * (D_INNER * D_STATE) + r;
        hs[o] = h;
        h = cA[o] * h + cH[o];
    }
}

// ---------------------------------------------------------------------------
// Scan part 3: replay with true start state, reduce over n, fused gate.
// ---------------------------------------------------------------------------
__global__ __launch_bounds__(256)
void scan_part3(const float* __restrict__ dbl,
                const float* __restrict__ xc,
                const float* __restrict__ xz,
                const float* __restrict__ A_log,
                const float* __restrict__ dpw,
                const float* __restrict__ dpb,
                const float* __restrict__ Dp,
                const float* __restrict__ hs,
                float* __restrict__ y)
{
    GRID_WAIT();
    __shared__ float s_dt[CLEN * 16];
    __shared__ float s_B [CLEN * 16];
    __shared__ float s_C [CLEN * 16];
    __shared__ float s_xc[CLEN * 16];
    __shared__ float s_dl[CLEN * 16];
    __shared__ float s_y [CLEN * 16];
    __shared__ float s_pw[16 * 17];

    int dg = blockIdx.x & 31;
    int c  = (blockIdx.x >> 5) & (NCHUNK - 1);
    int b  = blockIdx.x >> 10;
    int tid = threadIdx.x;
    int n  = tid & 15;
    int dl = tid >> 4;
    int d  = dg * 16 + dl;
    int l0 = c * CLEN;

    const float* dbl_p = dbl + ((size_t)b * SEQLEN + l0) * DBL_COLS;
    const float* xc_p  = xc  + ((size_t)b * SEQLEN + l0) * D_INNER + dg * 16;
    const float* z_p   = xz  + ((size_t)b * SEQLEN + l0) * 2 * D_INNER + D_INNER + dg * 16;
    float*       y_p   = y   + ((size_t)b * SEQLEN + l0) * D_INNER + dg * 16;

    for (int idx = tid; idx < CLEN * DBL_COLS; idx += 256) {
        int l = idx / DBL_COLS, cc = idx % DBL_COLS;
        float v = dbl_p[(size_t)l * DBL_COLS + cc];
        if      (cc < 16) s_dt[l * 16 + cc] = v;
        else if (cc < 32) s_B [l * 16 + (cc - 16)] = v;
        else              s_C [l * 16 + (cc - 32)] = v;
    }
    for (int idx = tid; idx < CLEN * 16; idx += 256) {
        int l = idx >> 4, dd = idx & 15;
        s_xc[l * 16 + dd] = xc_p[(size_t)l * D_INNER + dd];
    }
    {
        int rr = tid >> 4, cc = tid & 15;
        s_pw[rr * 17 + cc] = dpw[(size_t)(dg * 16 + rr) * DT_RANK + cc];
    }
    __syncthreads();

    for (int idx = tid; idx < CLEN * 16; idx += 256) {
        int l = idx >> 4, dd = idx & 15;
        float acc = dpb[dg * 16 + dd];
        #pragma unroll
        for (int r = 0; r < 16; r++)
            acc += s_dt[l * 16 + r] * s_pw[dd * 17 + r];
        s_dl[l * 16 + dd] = (acc > 20.f) ? acc : log1pf(__expf(acc));
    }
    __syncthreads();

    float Adn = -__expf(A_log[d * D_STATE + n]);
    float h = hs[(((size_t)b * NCHUNK + c) * D_INNER + d) * D_STATE + n];

    #pragma unroll 4
    for (int l = 0; l < CLEN; l++) {
        float dv = s_dl[l * 16 + dl];
        h = __expf(dv * Adn) * h + (dv * s_xc[l * 16 + dl]) * s_B[l * 16 + n];
        float p = h * s_C[l * 16 + n];
        p += __shfl_xor_sync(0xffffffffu, p, 8);
        p += __shfl_xor_sync(0xffffffffu, p, 4);
        p += __shfl_xor_sync(0xffffffffu, p, 2);
        p += __shfl_xor_sync(0xffffffffu, p, 1);
        if (n == 0) s_y[l * 16 + dl] = p;
    }
    __syncthreads();

    for (int idx = tid; idx < CLEN * 16; idx += 256) {
        int l = idx >> 4, dd = idx & 15;
        float z = z_p[(size_t)l * 2 * D_INNER + dd];
        float sz = z / (1.f + __expf(-z));
        y_p[(size_t)l * D_INNER + dd] =
            (s_y[l * 16 + dd] + s_xc[l * 16 + dd] * Dp[dg * 16 + dd]) * sz;
    }
}

// ---------------------------------------------------------------------------
// PDL launch helper
// ---------------------------------------------------------------------------
template <typename F, typename... Args>
static void launch_pdl(F* kern, dim3 grid, dim3 block, Args... args)
{
    cudaLaunchConfig_t cfg = {};
    cfg.gridDim = grid;
    cfg.blockDim = block;
    cfg.dynamicSmemBytes = 0;
    cudaLaunchAttribute attr[1];
    attr[0].id = cudaLaunchAttributeProgrammaticStreamSerialization;
    attr[0].val.programmaticStreamSerializationAllowed = 1;
    cfg.attrs = attr;
    cfg.numAttrs = 1;
    cudaLaunchKernelEx(&cfg, kern, args...);
}

// ---------------------------------------------------------------------------
// Launcher
// ---------------------------------------------------------------------------
extern "C" void kernel_launch(void* const* d_in, const int* in_sizes, int n_in,
                              void* d_out, int out_size)
{
    const float* x_in = (const float*)d_in[0];
    const float* ln_w = (const float*)d_in[1];
    const float* ln_b = (const float*)d_in[2];
    const float* ipw  = (const float*)d_in[3];
    const float* cw   = (const float*)d_in[4];
    const float* cb   = (const float*)d_in[5];
    const float* xpw  = (const float*)d_in[6];
    const float* dpw  = (const float*)d_in[7];
    const float* dpb  = (const float*)d_in[8];
    const float* alog = (const float*)d_in[9];
    const float* dpar = (const float*)d_in[10];
    const float* opw  = (const float*)d_in[11];
    float* xbuf = (float*)d_out;

    float *p_h, *p_xz, *p_xc, *p_dbl, *p_part, *p_y, *p_cA, *p_cH, *p_hs;
    cudaGetSymbolAddress((void**)&p_h,    g_h);
    cudaGetSymbolAddress((void**)&p_xz,   g_xz);
    cudaGetSymbolAddress((void**)&p_xc,   g_xc);
    cudaGetSymbolAddress((void**)&p_dbl,  g_dbl);
    cudaGetSymbolAddress((void**)&p_part, g_part);
    cudaGetSymbolAddress((void**)&p_y,    g_y);
    cudaGetSymbolAddress((void**)&p_cA,   g_cA);
    cudaGetSymbolAddress((void**)&p_cH,   g_cH);
    cudaGetSymbolAddress((void**)&p_hs,   g_hs);

    cudaMemcpyAsync(xbuf, x_in, (size_t)NTOK * D_MODEL * sizeof(float),
                    cudaMemcpyDeviceToDevice);

    const int EW_THREADS = 256;
    const int EW_BLOCKS  = (NTOK * D_INNER + EW_THREADS - 1) / EW_THREADS;
    const int SCAN_BLOCKS = BATCH * NCHUNK * 32;

    for (int layer = 0; layer < DEPTH; layer++) {
        const float* l_lnw  = ln_w + layer * D_MODEL;
        const float* l_lnb  = ln_b + layer * D_MODEL;
        const float* l_ipw  = ipw  + (size_t)layer * 2 * D_INNER * D_MODEL;
        const float* l_cw   = cw   + (size_t)layer * D_INNER * D_CONV;
        const float* l_cb   = cb   + (size_t)layer * D_INNER;
        const float* l_xpw  = xpw  + (size_t)layer * DBL_COLS * D_INNER;
        const float* l_dpw  = dpw  + (size_t)layer * D_INNER * DT_RANK;
        const float* l_dpb  = dpb  + (size_t)layer * D_INNER;
        const float* l_alog = alog + (size_t)layer * D_INNER * D_STATE;
        const float* l_dpar = dpar + (size_t)layer * D_INNER;
        const float* l_opw  = opw  + (size_t)layer * D_MODEL * D_INNER;

        // 1. LayerNorm
        launch_pdl(ln_kernel, dim3(NTOK), dim3(D_MODEL),
                   (const float*)xbuf, l_lnw, l_lnb, p_h);

        // 2. in_proj (BN=128 wide tile)
        launch_pdl(gemm_tf32<0, 8>, dim3(8, NTOK / 128, 1), dim3(256),
                   (const float*)p_h, D_MODEL, l_ipw, D_MODEL,
                   p_xz, 2 * D_INNER, 2 * D_INNER, D_MODEL, (size_t)0);

        // 3. conv + silu
        launch_pdl(conv_silu_kernel, dim3(EW_BLOCKS), dim3(EW_THREADS),
                   (const float*)p_xz, l_cw, l_cb, p_xc);

        // 4. x_proj split-K=4: partials, then reduce
        launch_pdl(gemm_tf32<0, 4>, dim3(1, NTOK / 128, XP_SK), dim3(256),
                   (const float*)p_xc, D_INNER, l_xpw, D_INNER,
                   p_part, DBL_COLS, DBL_COLS, D_INNER / XP_SK,
                   (size_t)NTOK * DBL_COLS);
        launch_pdl(reduce_dbl, dim3((NTOK * DBL_COLS + 255) / 256), dim3(256),
                   (const float*)p_part, p_dbl);

        // 5. chunked scan (delta fused) + gate
        launch_pdl(scan_part1, dim3(SCAN_BLOCKS), dim3(256),
                   (const float*)p_dbl, (const float*)p_xc, l_alog,
                   l_dpw, l_dpb, p_cA, p_cH);
        launch_pdl(scan_part2,
                   dim3((BATCH * D_INNER * D_STATE + 255) / 256), dim3(256),
                   (const float*)p_cA, (const float*)p_cH, p_hs);
        launch_pdl(scan_part3, dim3(SCAN_BLOCKS), dim3(256),
                   (const float*)p_dbl, (const float*)p_xc,
                   (const float*)p_xz, l_alog, l_dpw, l_dpb, l_dpar,
                   (const float*)p_hs, p_y);

        // 6. out_proj + residual
        launch_pdl(gemm_tf32<2, 4>, dim3(4, NTOK / 128, 1), dim3(256),
                   (const float*)p_y, D_INNER, l_opw, D_INNER,
                   xbuf, D_MODEL, D_MODEL, D_INNER, (size_t)0);
    }
}

// round 8
// speedup vs baseline: 1.2093x; 1.0168x over previous
#include <cuda_runtime.h>
#include <cuda_bf16.h>
#include <math.h>
#include <stdint.h>

// ---------------------------------------------------------------------------
#define D_MODEL   256
#define DEPTH     2
#define D_INNER   512
#define D_STATE   16
#define D_CONV    4
#define DT_RANK   16
#define BATCH     2
#define SEQLEN    2048
#define NTOK      (BATCH * SEQLEN)          // 4096
#define DBL_COLS  (DT_RANK + 2 * D_STATE)   // 48

#define NCHUNK    32
#define CLEN      (SEQLEN / NCHUNK)         // 64
#define XP_SK     4                          // x_proj split-K
#define NFLAGS    (BATCH * NCHUNK * 32)      // 2048 lookback flags

// PDL: wait for upstream kernel
#define GRID_WAIT() asm volatile("griddepcontrol.wait;" ::: "memory")

// ---------------------------------------------------------------------------
// Scratch
// ---------------------------------------------------------------------------
__device__ float g_h    [NTOK * D_MODEL];
__device__ float g_xz   [NTOK * 2 * D_INNER];
__device__ float g_xc   [NTOK * D_INNER];
__device__ float g_dbl  [NTOK * DBL_COLS];
__device__ float g_part [XP_SK * NTOK * DBL_COLS];
__device__ float g_y    [NTOK * D_INNER];
__device__ float g_cA   [BATCH * NCHUNK * D_INNER * D_STATE];
__device__ float g_cH   [BATCH * NCHUNK * D_INNER * D_STATE];
__device__ int   g_flag [NFLAGS];

// ---------------------------------------------------------------------------
// cp.async helpers
// ---------------------------------------------------------------------------
__device__ __forceinline__ uint32_t smem_u32(const void* p) {
    uint32_t a;
    asm("{.reg .u64 t; cvta.to.shared.u64 t, %1; cvt.u32.u64 %0, t;}"
        : "=r"(a) : "l"(p));
    return a;
}
__device__ __forceinline__ void cp_async16(void* dst, const void* src) {
    asm volatile("cp.async.ca.shared.global [%0], [%1], 16;"
                 :: "r"(smem_u32(dst)), "l"(src));
}
__device__ __forceinline__ void cp_async16_z(void* dst, const void* src, bool ok) {
    int sz = ok ? 16 : 0;
    asm volatile("cp.async.ca.shared.global [%0], [%1], 16, %2;"
                 :: "r"(smem_u32(dst)), "l"(src), "r"(sz));
}
#define CP_COMMIT() asm volatile("cp.async.commit_group;")
#define CP_WAIT0()  asm volatile("cp.async.wait_group 0;")

// ---------------------------------------------------------------------------
// LayerNorm: one block per token, 256 threads
// ---------------------------------------------------------------------------
__global__ void ln_kernel(const float* __restrict__ x,
                          const float* __restrict__ w,
                          const float* __restrict__ b,
                          float* __restrict__ out)
{
    GRID_WAIT();
    __shared__ float s_sum[8], s_sq[8];
    int t = blockIdx.x;
    int d = threadIdx.x;
    float v = x[t * D_MODEL + d];

    float s = v, q = v * v;
    #pragma unroll
    for (int o = 16; o > 0; o >>= 1) {
        s += __shfl_xor_sync(0xffffffffu, s, o);
        q += __shfl_xor_sync(0xffffffffu, q, o);
    }
    int warp = threadIdx.x >> 5;
    if ((threadIdx.x & 31) == 0) { s_sum[warp] = s; s_sq[warp] = q; }
    __syncthreads();
    if (threadIdx.x < 8) { s = s_sum[threadIdx.x]; q = s_sq[threadIdx.x]; }
    else                 { s = 0.f; q = 0.f; }
    if (warp == 0) {
        #pragma unroll
        for (int o = 4; o > 0; o >>= 1) {
            s += __shfl_xor_sync(0xffffffffu, s, o);
            q += __shfl_xor_sync(0xffffffffu, q, o);
        }
        if (threadIdx.x == 0) { s_sum[0] = s; s_sq[0] = q; }
    }
    __syncthreads();
    float mu  = s_sum[0] * (1.f / D_MODEL);
    float var = s_sq[0] * (1.f / D_MODEL) - mu * mu;
    float inv = rsqrtf(var + 1e-5f);
    out[t * D_MODEL + d] = (v - mu) * inv * w[d] + b[d];
}

// ---------------------------------------------------------------------------
// tf32 tensor-core GEMM (unchanged from R7)
// ---------------------------------------------------------------------------
template <int MODE, int NI>
__global__ __launch_bounds__(256)
void gemm_tf32(const float* __restrict__ A, int lda,
               const float* __restrict__ W, int ldw,
               float*       __restrict__ C, int ldc,
               int N, int K, size_t csplit)
{
    GRID_WAIT();
    const int BM = 128, BK = 16, LDS = 20;
    const int BN = 16 * NI;
    __shared__ uint32_t As[2][BM * LDS];
    __shared__ uint32_t Bs[2][BN * LDS];

    A += (size_t)blockIdx.z * K;
    C += (size_t)blockIdx.z * csplit;

    int tid  = threadIdx.x;
    int lane = tid & 31;
    int warp = tid >> 5;
    int m0 = blockIdx.y * BM;
    int n0 = blockIdx.x * BN;
    int wm = (warp >> 1) * 32;
    int wn = (warp & 1) * 8 * NI;
    int gr = lane >> 2;
    int gc = lane & 3;

    float acc[2][NI][4];
    #pragma unroll
    for (int mi = 0; mi < 2; mi++)
        #pragma unroll
        for (int ni = 0; ni < NI; ni++)
            #pragma unroll
            for (int e = 0; e < 4; e++) acc[mi][ni][e] = 0.f;

    int lrow = tid >> 2;
    int lcol = (tid & 3) * 4;

    auto issue = [&](int k0, int buf) {
        #pragma unroll
        for (int h = 0; h < 2; h++) {
            int r = lrow + h * 64;
            cp_async16(&As[buf][r * LDS + lcol],
                       &A[(size_t)(m0 + r) * lda + k0 + lcol]);
        }
        #pragma unroll
        for (int h = 0; h < NI / 4; h++) {
            int r = lrow + h * 64;
            bool ok = (n0 + r) < N;
            const float* src = ok ? &W[(size_t)(n0 + r) * ldw + k0 + lcol] : W;
            cp_async16_z(&Bs[buf][r * LDS + lcol], src, ok);
        }
    };

    int nk = K / BK;
    issue(0, 0);
    CP_COMMIT();

    for (int i = 0; i < nk; i++) {
        CP_WAIT0();
        __syncthreads();
        if (i + 1 < nk) { issue((i + 1) * BK, (i + 1) & 1); CP_COMMIT(); }
        int buf = i & 1;

        #pragma unroll
        for (int ks = 0; ks < BK; ks += 8) {
            uint32_t a[2][4], b[NI][2];
            #pragma unroll
            for (int mi = 0; mi < 2; mi++) {
                int rb = wm + mi * 16 + gr;
                a[mi][0] = As[buf][rb * LDS + ks + gc];
                a[mi][1] = As[buf][(rb + 8) * LDS + ks + gc];
                a[mi][2] = As[buf][rb * LDS + ks + gc + 4];
                a[mi][3] = As[buf][(rb + 8) * LDS + ks + gc + 4];
            }
            #pragma unroll
            for (int ni = 0; ni < NI; ni++) {
                int rb = wn + ni * 8 + gr;
                b[ni][0] = Bs[buf][rb * LDS + ks + gc];
                b[ni][1] = Bs[buf][rb * LDS + ks + gc + 4];
            }
            #pragma unroll
            for (int mi = 0; mi < 2; mi++)
                #pragma unroll
                for (int ni = 0; ni < NI; ni++)
                    asm volatile(
                        "mma.sync.aligned.m16n8k8.row.col.f32.tf32.tf32.f32 "
                        "{%0,%1,%2,%3}, {%4,%5,%6,%7}, {%8,%9}, {%0,%1,%2,%3};"
                        : "+f"(acc[mi][ni][0]), "+f"(acc[mi][ni][1]),
                          "+f"(acc[mi][ni][2]), "+f"(acc[mi][ni][3])
                        : "r"(a[mi][0]), "r"(a[mi][1]), "r"(a[mi][2]), "r"(a[mi][3]),
                          "r"(b[ni][0]), "r"(b[ni][1]));
        }
    }

    #pragma unroll
    for (int mi = 0; mi < 2; mi++) {
        #pragma unroll
        for (int ni = 0; ni < NI; ni++) {
            int col = n0 + wn + ni * 8 + gc * 2;
            if (col < N) {
                #pragma unroll
                for (int half = 0; half < 2; half++) {
                    int row = m0 + wm + mi * 16 + gr + half * 8;
                    float2 v = make_float2(acc[mi][ni][half * 2],
                                           acc[mi][ni][half * 2 + 1]);
                    float2* cp = (float2*)&C[(size_t)row * ldc + col];
                    if (MODE == 2) {
                        float2 o = *cp;
                        v.x += o.x; v.y += o.y;
                    }
                    *cp = v;
                }
            }
        }
    }
}

// ---------------------------------------------------------------------------
// Reduce x_proj split-K partials + zero the lookback flags for the scan
// ---------------------------------------------------------------------------
__global__ void reduce_dbl(const float* __restrict__ part,
                           float* __restrict__ dbl,
                           int* __restrict__ flags)
{
    GRID_WAIT();
    int i = blockIdx.x * 256 + threadIdx.x;
    if (i < NFLAGS) flags[i] = 0;
    if (i < NTOK * DBL_COLS) {
        float s = part[i];
        #pragma unroll
        for (int z = 1; z < XP_SK; z++)
            s += part[(size_t)z * NTOK * DBL_COLS + i];
        dbl[i] = s;
    }
}

// ---------------------------------------------------------------------------
// Depthwise causal conv (D_CONV=4) + SiLU
// ---------------------------------------------------------------------------
__global__ void conv_silu_kernel(const float* __restrict__ xz,
                                 const float* __restrict__ cw,
                                 const float* __restrict__ cb,
                                 float* __restrict__ xc)
{
    GRID_WAIT();
    int idx = blockIdx.x * blockDim.x + threadIdx.x;
    if (idx >= NTOK * D_INNER) return;
    int d = idx & (D_INNER - 1);
    int t = idx >> 9;
    int l = t & (SEQLEN - 1);

    float acc = cb[d];
    #pragma unroll
    for (int k = 0; k < D_CONV; k++) {
        int ll = l - (D_CONV - 1) + k;
        if (ll >= 0)
            acc += xz[(size_t)(t - (D_CONV - 1) + k) * (2 * D_INNER) + d] * cw[d * D_CONV + k];
    }
    float sg = 1.f / (1.f + __expf(-acc));
    xc[idx] = acc * sg;
}

// ---------------------------------------------------------------------------
// Fused selective scan: local scan -> publish -> lookback -> replay -> gate.
// Grid 2048 blocks = (b, c, dg); block 256 threads = 16 d x 16 n.
// Deadlock-free: block (b,c,dg) polls only flags of strictly lower blockIdx.
// ---------------------------------------------------------------------------
__global__ __launch_bounds__(256)
void scan_fused(const float* __restrict__ dbl,
                const float* __restrict__ xc,
                const float* __restrict__ xz,
                const float* __restrict__ A_log,
                const float* __restrict__ dpw,
                const float* __restrict__ dpb,
                const float* __restrict__ Dp,
                float* __restrict__ cA,
                float* __restrict__ cH,
                int*   __restrict__ flags,
                float* __restrict__ y)
{
    GRID_WAIT();
    __shared__ float s_dt[CLEN * 16];         // reused as s_y after delta
    __shared__ float s_B [CLEN * 16];
    __shared__ float s_C [CLEN * 16];
    __shared__ float s_xc[CLEN * 16];
    __shared__ float s_dl[CLEN * 16];
    __shared__ float s_pw[16 * 17];
    float* s_y = s_dt;

    int dg = blockIdx.x & 31;
    int c  = (blockIdx.x >> 5) & (NCHUNK - 1);
    int b  = blockIdx.x >> 10;
    int tid = threadIdx.x;
    int n  = tid & 15;
    int dl = tid >> 4;
    int d  = dg * 16 + dl;
    int l0 = c * CLEN;

    const float* dbl_p = dbl + ((size_t)b * SEQLEN + l0) * DBL_COLS;
    const float* xc_p  = xc  + ((size_t)b * SEQLEN + l0) * D_INNER + dg * 16;

    // ---- stage ----
    for (int idx = tid; idx < CLEN * DBL_COLS; idx += 256) {
        int l = idx / DBL_COLS, cc = idx % DBL_COLS;
        float v = dbl_p[(size_t)l * DBL_COLS + cc];
        if      (cc < 16) s_dt[l * 16 + cc] = v;
        else if (cc < 32) s_B [l * 16 + (cc - 16)] = v;
        else              s_C [l * 16 + (cc - 32)] = v;
    }
    for (int idx = tid; idx < CLEN * 16; idx += 256) {
        int l = idx >> 4, dd = idx & 15;
        s_xc[l * 16 + dd] = xc_p[(size_t)l * D_INNER + dd];
    }
    {
        int rr = tid >> 4, cc = tid & 15;
        s_pw[rr * 17 + cc] = dpw[(size_t)(dg * 16 + rr) * DT_RANK + cc];
    }
    __syncthreads();

    // ---- delta (consumes s_dt) ----
    for (int idx = tid; idx < CLEN * 16; idx += 256) {
        int l = idx >> 4, dd = idx & 15;
        float acc = dpb[dg * 16 + dd];
        #pragma unroll
        for (int r = 0; r < 16; r++)
            acc += s_dt[l * 16 + r] * s_pw[dd * 17 + r];
        s_dl[l * 16 + dd] = (acc > 20.f) ? acc : log1pf(__expf(acc));
    }
    __syncthreads();   // s_dt now dead -> becomes s_y

    float Adn = -__expf(A_log[d * D_STATE + n]);

    // ---- local scan (h0 = 0) ----
    float hloc = 0.f, P = 1.f;
    #pragma unroll 8
    for (int l = 0; l < CLEN; l++) {
        float dv = s_dl[l * 16 + dl];
        float a  = __expf(dv * Adn);
        hloc = a * hloc + (dv * s_xc[l * 16 + dl]) * s_B[l * 16 + n];
        P *= a;
    }

    // ---- publish local summary ----
    size_t col_base = (((size_t)b * NCHUNK) * D_INNER + d) * D_STATE + n;
    size_t cstride  = (size_t)D_INNER * D_STATE;
    cA[col_base + (size_t)c * cstride] = P;
    cH[col_base + (size_t)c * cstride] = hloc;
    __threadfence();
    __syncthreads();
    if (tid == 0) {
        int* fp = &flags[(b * NCHUNK + c) * 32 + dg];
        asm volatile("st.release.gpu.b32 [%0], %1;" :: "l"(fp), "r"(1) : "memory");
    }

    // ---- lookback: wait for chunks 0..c-1, combine in order ----
    float h = 0.f;
    if (c > 0) {
        if (tid < c) {
            const int* fp = &flags[(b * NCHUNK + tid) * 32 + dg];
            int v;
            do {
                asm volatile("ld.acquire.gpu.b32 %0, [%1];" : "=r"(v) : "l"(fp) : "memory");
            } while (v == 0);
        }
        __syncthreads();
        for (int j = 0; j < c; j++) {
            size_t o = col_base + (size_t)j * cstride;
            h = cA[o] * h + cH[o];
        }
    }

    // ---- replay with true start state + n-reduction ----
    #pragma unroll 4
    for (int l = 0; l < CLEN; l++) {
        float dv = s_dl[l * 16 + dl];
        h = __expf(dv * Adn) * h + (dv * s_xc[l * 16 + dl]) * s_B[l * 16 + n];
        float p = h * s_C[l * 16 + n];
        p += __shfl_xor_sync(0xffffffffu, p, 8);
        p += __shfl_xor_sync(0xffffffffu, p, 4);
        p += __shfl_xor_sync(0xffffffffu, p, 2);
        p += __shfl_xor_sync(0xffffffffu, p, 1);
        if (n == 0) s_y[l * 16 + dl] = p;
    }
    __syncthreads();

    // ---- gate + write ----
    const float* z_p = xz + ((size_t)b * SEQLEN + l0) * 2 * D_INNER + D_INNER + dg * 16;
    float*       y_p = y  + ((size_t)b * SEQLEN + l0) * D_INNER + dg * 16;
    for (int idx = tid; idx < CLEN * 16; idx += 256) {
        int l = idx >> 4, dd = idx & 15;
        float z = z_p[(size_t)l * 2 * D_INNER + dd];
        float sz = z / (1.f + __expf(-z));
        y_p[(size_t)l * D_INNER + dd] =
            (s_y[l * 16 + dd] + s_xc[l * 16 + dd] * Dp[dg * 16 + dd]) * sz;
    }
}

// ---------------------------------------------------------------------------
// PDL launch helper
// ---------------------------------------------------------------------------
template <typename F, typename... Args>
static void launch_pdl(F* kern, dim3 grid, dim3 block, Args... args)
{
    cudaLaunchConfig_t cfg = {};
    cfg.gridDim = grid;
    cfg.blockDim = block;
    cfg.dynamicSmemBytes = 0;
    cudaLaunchAttribute attr[1];
    attr[0].id = cudaLaunchAttributeProgrammaticStreamSerialization;
    attr[0].val.programmaticStreamSerializationAllowed = 1;
    cfg.attrs = attr;
    cfg.numAttrs = 1;
    cudaLaunchKernelEx(&cfg, kern, args...);
}

// ---------------------------------------------------------------------------
// Launcher
// ---------------------------------------------------------------------------
extern "C" void kernel_launch(void* const* d_in, const int* in_sizes, int n_in,
                              void* d_out, int out_size)
{
    const float* x_in = (const float*)d_in[0];
    const float* ln_w = (const float*)d_in[1];
    const float* ln_b = (const float*)d_in[2];
    const float* ipw  = (const float*)d_in[3];
    const float* cw   = (const float*)d_in[4];
    const float* cb   = (const float*)d_in[5];
    const float* xpw  = (const float*)d_in[6];
    const float* dpw  = (const float*)d_in[7];
    const float* dpb  = (const float*)d_in[8];
    const float* alog = (const float*)d_in[9];
    const float* dpar = (const float*)d_in[10];
    const float* opw  = (const float*)d_in[11];
    float* xbuf = (float*)d_out;

    float *p_h, *p_xz, *p_xc, *p_dbl, *p_part, *p_y, *p_cA, *p_cH;
    int* p_flag;
    cudaGetSymbolAddress((void**)&p_h,    g_h);
    cudaGetSymbolAddress((void**)&p_xz,   g_xz);
    cudaGetSymbolAddress((void**)&p_xc,   g_xc);
    cudaGetSymbolAddress((void**)&p_dbl,  g_dbl);
    cudaGetSymbolAddress((void**)&p_part, g_part);
    cudaGetSymbolAddress((void**)&p_y,    g_y);
    cudaGetSymbolAddress((void**)&p_cA,   g_cA);
    cudaGetSymbolAddress((void**)&p_cH,   g_cH);
    cudaGetSymbolAddress((void**)&p_flag, g_flag);

    cudaMemcpyAsync(xbuf, x_in, (size_t)NTOK * D_MODEL * sizeof(float),
                    cudaMemcpyDeviceToDevice);

    const int EW_THREADS = 256;
    const int EW_BLOCKS  = (NTOK * D_INNER + EW_THREADS - 1) / EW_THREADS;
    const int SCAN_BLOCKS = BATCH * NCHUNK * 32;

    for (int layer = 0; layer < DEPTH; layer++) {
        const float* l_lnw  = ln_w + layer * D_MODEL;
        const float* l_lnb  = ln_b + layer * D_MODEL;
        const float* l_ipw  = ipw  + (size_t)layer * 2 * D_INNER * D_MODEL;
        const float* l_cw   = cw   + (size_t)layer * D_INNER * D_CONV;
        const float* l_cb   = cb   + (size_t)layer * D_INNER;
        const float* l_xpw  = xpw  + (size_t)layer * DBL_COLS * D_INNER;
        const float* l_dpw  = dpw  + (size_t)layer * D_INNER * DT_RANK;
        const float* l_dpb  = dpb  + (size_t)layer * D_INNER;
        const float* l_alog = alog + (size_t)layer * D_INNER * D_STATE;
        const float* l_dpar = dpar + (size_t)layer * D_INNER;
        const float* l_opw  = opw  + (size_t)layer * D_MODEL * D_INNER;

        // 1. LayerNorm
        launch_pdl(ln_kernel, dim3(NTOK), dim3(D_MODEL),
                   (const float*)xbuf, l_lnw, l_lnb, p_h);

        // 2. in_proj (BN=128 wide tile)
        launch_pdl(gemm_tf32<0, 8>, dim3(8, NTOK / 128, 1), dim3(256),
                   (const float*)p_h, D_MODEL, l_ipw, D_MODEL,
                   p_xz, 2 * D_INNER, 2 * D_INNER, D_MODEL, (size_t)0);

        // 3. conv + silu
        launch_pdl(conv_silu_kernel, dim3(EW_BLOCKS), dim3(EW_THREADS),
                   (const float*)p_xz, l_cw, l_cb, p_xc);

        // 4. x_proj split-K=4: partials, then reduce (+ flag reset)
        launch_pdl(gemm_tf32<0, 4>, dim3(1, NTOK / 128, XP_SK), dim3(256),
                   (const float*)p_xc, D_INNER, l_xpw, D_INNER,
                   p_part, DBL_COLS, DBL_COLS, D_INNER / XP_SK,
                   (size_t)NTOK * DBL_COLS);
        launch_pdl(reduce_dbl, dim3((NTOK * DBL_COLS + 255) / 256), dim3(256),
                   (const float*)p_part, p_dbl, p_flag);

        // 5. fused scan (local + lookback + replay + gate)
        launch_pdl(scan_fused, dim3(SCAN_BLOCKS), dim3(256),
                   (const float*)p_dbl, (const float*)p_xc,
                   (const float*)p_xz, l_alog, l_dpw, l_dpb, l_dpar,
                   p_cA, p_cH, p_flag, p_y);

        // 6. out_proj + residual
        launch_pdl(gemm_tf32<2, 4>, dim3(4, NTOK / 128, 1), dim3(256),
                   (const float*)p_y, D_INNER, l_opw, D_INNER,
                   xbuf, D_MODEL, D_MODEL, D_INNER, (size_t)0);
    }
}